// round 17
// baseline (speedup 1.0000x reference)
#include <cuda_runtime.h>
#include <cuda_bf16.h>
#include <cuda_fp16.h>
#include <cstdint>

#define M_DIM 64
#define K_DIM 8192
#define N_DIM 8192
#define KBLK  16
#define NTILE 128
#define KSPLIT 4
#define KC    32
#define ITERS ((K_DIM / KSPLIT) / KC)   /* 64 */
#define THREADS 256
#define STR   40      /* halves per fp16 smem row (80B): ldmatrix conflict-free */

/* smem layout (bytes) */
#define WC_OFF 0                        /* raw W codes ring: 3 x 16384 */
#define XH_OFF 49152                    /* X hi ring: 3 x 5120 */
#define XL_OFF (XH_OFF + 15360)         /* X lo ring: 3 x 5120 */
#define WS_OFF (XL_OFF + 15360)         /* W scale ring: 3 x 1024 */
#define WH_OFF (WS_OFF + 3072)          /* decoded W hi: 10240 (single buf) */
#define WL_OFF (WH_OFF + 10240)         /* decoded W lo: 10240 */
#define SMEM_BYTES (WL_OFF + 10240)     /* 103424 */

__device__ float  g_scratch[KSPLIT * M_DIM * N_DIM];  // 8 MB fp32 partial slabs
__device__ __half g_xh[M_DIM * K_DIM];   // x hi (scale folded, x4096, fp16-exact)
__device__ __half g_xl[M_DIM * K_DIM];   // x lo correction

__constant__ float c_lut[16] = { 0.f, 0.5f, 1.f, 1.5f, 2.f, 3.f, 4.f, 6.f,
                                -0.f,-0.5f,-1.f,-1.5f,-2.f,-3.f,-4.f,-6.f};

// ---------------------------------------------------------------------------
// Kernel A: x codes -> (xh, xl) fp16, block scale folded (R16-validated).
// ---------------------------------------------------------------------------
__global__ void prep_kernel(const int* __restrict__ x, const float* __restrict__ xs) {
    int t    = blockIdx.x * blockDim.x + threadIdx.x;   // < M*K/4
    int lane = threadIdx.x & 31;
    float lutv = c_lut[lane & 15];
    int4 c = ((const int4*)x)[t];
    int k4 = t & (K_DIM / 4 - 1);
    int m  = t >> 11;
    float s  = xs[m * (K_DIM / KBLK) + (k4 >> 2)];
    float sb = s * 4096.0f;
    float sh = __uint_as_float(__float_as_uint(sb) & 0xFFFF8000u);
    float sl = sb - sh;
    float v0 = __shfl_sync(0xffffffffu, lutv, c.x & 15);
    float v1 = __shfl_sync(0xffffffffu, lutv, c.y & 15);
    float v2 = __shfl_sync(0xffffffffu, lutv, c.z & 15);
    float v3 = __shfl_sync(0xffffffffu, lutv, c.w & 15);
    __half2 h0 = __floats2half2_rn(v0 * sh, v1 * sh);
    __half2 h1 = __floats2half2_rn(v2 * sh, v3 * sh);
    __half2 l0 = __floats2half2_rn(v0 * sl, v1 * sl);
    __half2 l1 = __floats2half2_rn(v2 * sl, v3 * sl);
    ((__half2*)g_xh)[t * 2    ] = h0;
    ((__half2*)g_xh)[t * 2 + 1] = h1;
    ((__half2*)g_xl)[t * 2    ] = l0;
    ((__half2*)g_xl)[t * 2 + 1] = l1;
}

// ---------------------------------------------------------------------------
// Kernel B: hi/lo fp16 HMMA GEMM fed by a 3-deep cp.async pipeline.
// Math identical to R16 (rel_err 2.18e-4). W codes ring -> decode-from-smem
// -> single-buffered Wh/Wl; X hi/lo cp.async straight into ldmatrix layout.
// ---------------------------------------------------------------------------
__global__ void __launch_bounds__(THREADS, 2)
gemm_kernel(const int* __restrict__ w, const float* __restrict__ wsc) {
    extern __shared__ char smem[];

    const int tid  = threadIdx.x;
    const int lane = tid & 31;
    const int warp = tid >> 5;
    const int bn   = blockIdx.x;
    const int k0   = blockIdx.y * (K_DIM / KSPLIT);
    const float lutv = c_lut[lane & 15];

    float acc[8][4];
    #pragma unroll
    for (int j = 0; j < 8; ++j)
        #pragma unroll
        for (int q = 0; q < 4; ++q) acc[j][q] = 0.f;

    // ---- one cp.async stage: W codes (16KB) + X hi/lo (8KB) + scales (1KB)
    #define ISSUE_STAGE(it)                                                        \
    {                                                                              \
        const int slot = (it) % 3;                                                 \
        const int kb   = k0 + (it) * KC;                                           \
        _Pragma("unroll")                                                          \
        for (int t = 0; t < 4; ++t) {                                              \
            int p = tid + t * 256;                                                 \
            int row = p >> 3, kc4 = p & 7;                                         \
            const int* src = w + (long)(bn * NTILE + row) * K_DIM + kb + kc4 * 4;  \
            unsigned d = (unsigned)__cvta_generic_to_shared(                       \
                smem + WC_OFF + slot * 16384 + row * 128 + kc4 * 16);              \
            asm volatile("cp.async.cg.shared.global [%0], [%1], 16;\n"             \
                         :: "r"(d), "l"(src) : "memory");                          \
        }                                                                          \
        {                                                                          \
            int row = tid >> 2, seg = tid & 3;                                     \
            const __half* sh_ = g_xh + row * K_DIM + kb + seg * 8;                 \
            const __half* sl_ = g_xl + row * K_DIM + kb + seg * 8;                 \
            unsigned dh = (unsigned)__cvta_generic_to_shared(                      \
                smem + XH_OFF + slot * 5120 + row * 80 + seg * 16);                \
            unsigned dl = (unsigned)__cvta_generic_to_shared(                      \
                smem + XL_OFF + slot * 5120 + row * 80 + seg * 16);                \
            asm volatile("cp.async.cg.shared.global [%0], [%1], 16;\n"             \
                         :: "r"(dh), "l"(sh_) : "memory");                         \
            asm volatile("cp.async.cg.shared.global [%0], [%1], 16;\n"             \
                         :: "r"(dl), "l"(sl_) : "memory");                         \
        }                                                                          \
        if (tid < 128) {                                                           \
            const float* src = wsc + (long)(bn * NTILE + tid) * (K_DIM / KBLK)     \
                                   + (kb >> 4);                                    \
            unsigned d = (unsigned)__cvta_generic_to_shared(                       \
                smem + WS_OFF + slot * 1024 + tid * 8);                            \
            asm volatile("cp.async.ca.shared.global [%0], [%1], 8;\n"              \
                         :: "r"(d), "l"(src) : "memory");                          \
        }                                                                          \
        asm volatile("cp.async.commit_group;\n" ::: "memory");                     \
    }

    // ldmatrix lane addressing (R8/R16-validated), 80B rows:
    const int aOff = (lane & 15) * 80 + ((lane & 16) ? 16 : 0);
    const int bOff = (lane & 7)  * 80 + ((lane & 8)  ? 16 : 0);

    ISSUE_STAGE(0);
    ISSUE_STAGE(1);

    for (int it = 0; it < ITERS; ++it) {
        const int slot = it % 3;
        asm volatile("cp.async.wait_group %0;\n" :: "n"(1) : "memory");
        __syncthreads();   // stage `it` visible to all; prior mma done -> Wh/Wl free

        // ---- decode W codes (smem) -> Wh/Wl fp16 (single buffer) ----
        {
            const char*  WCs = smem + WC_OFF + slot * 16384;
            const float* WSs = (const float*)(smem + WS_OFF + slot * 1024);
            char* WhB = smem + WH_OFF;
            char* WlB = smem + WL_OFF;
            #pragma unroll
            for (int t = 0; t < 4; ++t) {
                int p = tid + t * 256;
                int row = p >> 3, kc4 = p & 7;
                int4 cv = *(const int4*)(WCs + row * 128 + kc4 * 16);
                float sb = WSs[row * 2 + (kc4 >> 2)] * 4096.0f;
                float sh = __uint_as_float(__float_as_uint(sb) & 0xFFFF8000u);
                float sl = sb - sh;
                float v0 = __shfl_sync(0xffffffffu, lutv, cv.x & 15);
                float v1 = __shfl_sync(0xffffffffu, lutv, cv.y & 15);
                float v2 = __shfl_sync(0xffffffffu, lutv, cv.z & 15);
                float v3 = __shfl_sync(0xffffffffu, lutv, cv.w & 15);
                __half2 h0 = __floats2half2_rn(v0 * sh, v1 * sh);
                __half2 h1 = __floats2half2_rn(v2 * sh, v3 * sh);
                __half2 l0 = __floats2half2_rn(v0 * sl, v1 * sl);
                __half2 l1 = __floats2half2_rn(v2 * sl, v3 * sl);
                *(uint2*)(WhB + row * 80 + kc4 * 8) =
                    make_uint2(*(unsigned*)&h0, *(unsigned*)&h1);
                *(uint2*)(WlB + row * 80 + kc4 * 8) =
                    make_uint2(*(unsigned*)&l0, *(unsigned*)&l1);
            }
        }
        __syncthreads();

        if (it + 2 < ITERS) { ISSUE_STAGE(it + 2); }
        else { asm volatile("cp.async.commit_group;\n" ::: "memory"); }

        // ---- mma over this chunk ----
        const unsigned aBaseH = (unsigned)__cvta_generic_to_shared(
            smem + WH_OFF + warp * 16 * 80 + aOff);
        const unsigned aBaseL = aBaseH + (WL_OFF - WH_OFF);
        const unsigned bBaseH = (unsigned)__cvta_generic_to_shared(
            smem + XH_OFF + slot * 5120 + bOff);
        const unsigned bBaseL = bBaseH + (XL_OFF - XH_OFF);

        #pragma unroll
        for (int kk = 0; kk < 2; ++kk) {
            unsigned ah0, ah1, ah2, ah3, al0, al1, al2, al3;
            asm volatile(
                "ldmatrix.sync.aligned.m8n8.x4.shared.b16 {%0,%1,%2,%3}, [%4];\n"
                : "=r"(ah0), "=r"(ah1), "=r"(ah2), "=r"(ah3)
                : "r"(aBaseH + kk * 32));
            asm volatile(
                "ldmatrix.sync.aligned.m8n8.x4.shared.b16 {%0,%1,%2,%3}, [%4];\n"
                : "=r"(al0), "=r"(al1), "=r"(al2), "=r"(al3)
                : "r"(aBaseL + kk * 32));
            #pragma unroll
            for (int j = 0; j < 8; ++j) {
                unsigned bh0, bh1, bl0, bl1;
                asm volatile(
                    "ldmatrix.sync.aligned.m8n8.x2.shared.b16 {%0,%1}, [%2];\n"
                    : "=r"(bh0), "=r"(bh1)
                    : "r"(bBaseH + j * (8 * 80) + kk * 32));
                asm volatile(
                    "ldmatrix.sync.aligned.m8n8.x2.shared.b16 {%0,%1}, [%2];\n"
                    : "=r"(bl0), "=r"(bl1)
                    : "r"(bBaseL + j * (8 * 80) + kk * 32));
                asm volatile(
                    "mma.sync.aligned.m16n8k16.row.col.f32.f16.f16.f32 "
                    "{%0,%1,%2,%3}, {%4,%5,%6,%7}, {%8,%9}, {%0,%1,%2,%3};\n"
                    : "+f"(acc[j][0]), "+f"(acc[j][1]), "+f"(acc[j][2]), "+f"(acc[j][3])
                    : "r"(ah0), "r"(ah1), "r"(ah2), "r"(ah3), "r"(bh0), "r"(bh1));
                asm volatile(
                    "mma.sync.aligned.m16n8k16.row.col.f32.f16.f16.f32 "
                    "{%0,%1,%2,%3}, {%4,%5,%6,%7}, {%8,%9}, {%0,%1,%2,%3};\n"
                    : "+f"(acc[j][0]), "+f"(acc[j][1]), "+f"(acc[j][2]), "+f"(acc[j][3])
                    : "r"(ah0), "r"(ah1), "r"(ah2), "r"(ah3), "r"(bl0), "r"(bl1));
                asm volatile(
                    "mma.sync.aligned.m16n8k16.row.col.f32.f16.f16.f32 "
                    "{%0,%1,%2,%3}, {%4,%5,%6,%7}, {%8,%9}, {%0,%1,%2,%3};\n"
                    : "+f"(acc[j][0]), "+f"(acc[j][1]), "+f"(acc[j][2]), "+f"(acc[j][3])
                    : "r"(al0), "r"(al1), "r"(al2), "r"(al3), "r"(bh0), "r"(bh1));
            }
        }
    }

    // ---- epilogue (validated D mapping) ----
    const int gid = lane >> 2;
    const int tg  = lane & 3;
    float* S = g_scratch + blockIdx.y * (M_DIM * N_DIM);
    const int nbase = bn * NTILE + warp * 16 + gid;
    #pragma unroll
    for (int j = 0; j < 8; ++j) {
        const int m0 = j * 8 + tg * 2;
        S[(m0    ) * N_DIM + nbase    ] = acc[j][0];
        S[(m0 + 1) * N_DIM + nbase    ] = acc[j][1];
        S[(m0    ) * N_DIM + nbase + 8] = acc[j][2];
        S[(m0 + 1) * N_DIM + nbase + 8] = acc[j][3];
    }
    #undef ISSUE_STAGE
}

// ---------------------------------------------------------------------------
// Kernel C: out (fp32 buffer) = fp32(bf16(sum_slabs * gx*gw/2^24 + bias[n]))
// ---------------------------------------------------------------------------
__global__ void finalize_kernel(const float* __restrict__ g1,
                                const float* __restrict__ g2,
                                const float* __restrict__ bias,
                                float* __restrict__ out) {
    int idx = blockIdx.x * blockDim.x + threadIdx.x;
    if (idx >= M_DIM * N_DIM) return;
    const float g = g1[0] * g2[0] * (1.0f / 16777216.0f);
    const int n = idx & (N_DIM - 1);
    float s = 0.f;
    #pragma unroll
    for (int t = 0; t < KSPLIT; ++t)
        s += g_scratch[idx + t * (M_DIM * N_DIM)];
    float v = fmaf(s, g, bias[n]);
    out[idx] = __bfloat162float(__float2bfloat16(v));
}

// ---------------------------------------------------------------------------
// Inputs identified by element count (all distinct; byte-count fallback).
// ---------------------------------------------------------------------------
extern "C" void kernel_launch(void* const* d_in, const int* in_sizes, int n_in,
                              void* d_out, int out_size) {
    const int*   x    = nullptr;
    const float* xs   = nullptr;
    const int*   wgt  = nullptr;
    const float* wsc  = nullptr;
    const float* bias = nullptr;
    const float* gA   = nullptr;
    const float* gB   = nullptr;

    for (int pass = 0; pass < 2 && !wgt; ++pass) {
        const int mul = (pass == 0) ? 1 : 4;
        x = nullptr; xs = nullptr; wgt = nullptr; wsc = nullptr;
        bias = nullptr; gA = nullptr; gB = nullptr;
        for (int i = 0; i < n_in; ++i) {
            long sz = (long)in_sizes[i];
            if      (sz == (long)M_DIM * K_DIM * mul)          x    = (const int*)  d_in[i];
            else if (sz == (long)M_DIM * (K_DIM/KBLK) * mul)   xs   = (const float*)d_in[i];
            else if (sz == (long)N_DIM * K_DIM * mul)          wgt  = (const int*)  d_in[i];
            else if (sz == (long)N_DIM * (K_DIM/KBLK) * mul)   wsc  = (const float*)d_in[i];
            else if (sz == (long)N_DIM * mul)                  bias = (const float*)d_in[i];
            else if (sz == 1 * mul) { if (!gA) gA = (const float*)d_in[i];
                                      else     gB = (const float*)d_in[i]; }
        }
    }

    cudaFuncSetAttribute(gemm_kernel,
                         cudaFuncAttributeMaxDynamicSharedMemorySize, SMEM_BYTES);

    prep_kernel<<<(M_DIM * K_DIM / 4) / THREADS, THREADS>>>(x, xs);
    gemm_kernel<<<dim3(N_DIM / NTILE, KSPLIT), THREADS, SMEM_BYTES>>>(wgt, wsc);
    finalize_kernel<<<(M_DIM * N_DIM) / 256, 256>>>(gA, gB, bias,
                                                    (float*)d_out);
}